// round 10
// baseline (speedup 1.0000x reference)
#include <cuda_runtime.h>
#include <cuda_bf16.h>

// Problem: o [N=16, C=32, D=32, H=64, W=64] fp32, bias [C] fp32.
// out[n] = (1/(2*16384)) * sum_{c, pooled cells} max_{2x2x2}(o) + sum_c bias_c
// Pure HBM-streaming reduction: 256 MB in, 64 B out.
//
// R5 (= R4 resubmit, container infra failure): R1's streaming geometry
// (8192 x 32KB blocks, 7 waves for load-balance) + fire-and-forget REDG
// epilogue (no fence, no return-atomic, blocks retire instantly). Block
// (0,0,0) is also the finisher: it spins on a release/acquire counter, then
// writes out[] and resets scratch (graph-replay safe).

#define N_  16
#define C_  32
#define D_  32
#define H_  64
#define W_  64
#define PD_ (D_/2)
#define TOTAL_BLOCKS (N_ * C_ * PD_)   // 8192
// scale = 1/DIVISOR * 1/(PD*PH*PW) = 1/2 * 1/16384
#define SCALE_ (1.0f / 32768.0f)

// Persistent scratch (zero at module load; finisher resets every call).
__device__ float        g_scratch[N_];
__device__ unsigned int g_done;

__global__ __launch_bounds__(256, 8)
void fused_pool_reduce_kernel(const float* __restrict__ o,
                              const float* __restrict__ bias,
                              float* __restrict__ out) {
    const int pd = blockIdx.x;   // 0..15
    const int c  = blockIdx.y;   // 0..31
    const int n  = blockIdx.z;   // 0..15
    const int tid = threadIdx.x; // 0..255

    // Base of this (n,c) volume + the 2 D-slices d = 2*pd, 2*pd+1.
    const size_t vol_base = (((size_t)n * C_ + c) * D_ + 2 * pd) * (H_ * W_);
    const float* base = o + vol_base;

    // Work items: PH(32) x (W/4=16) = 512 tiles; 256 threads -> 2 each.
    const int item0 = tid;
    const int item1 = tid + 256;
    const int r0 = ((item0 >> 4) * 2) * W_ + (item0 & 15) * 4;
    const int r1 = ((item1 >> 4) * 2) * W_ + (item1 & 15) * 4;

    const float4 a00 = *reinterpret_cast<const float4*>(base + r0);
    const float4 a01 = *reinterpret_cast<const float4*>(base + r0 + W_);
    const float4 a02 = *reinterpret_cast<const float4*>(base + r0 + H_ * W_);
    const float4 a03 = *reinterpret_cast<const float4*>(base + r0 + H_ * W_ + W_);
    const float4 a10 = *reinterpret_cast<const float4*>(base + r1);
    const float4 a11 = *reinterpret_cast<const float4*>(base + r1 + W_);
    const float4 a12 = *reinterpret_cast<const float4*>(base + r1 + H_ * W_);
    const float4 a13 = *reinterpret_cast<const float4*>(base + r1 + H_ * W_ + W_);

    float m0x = fmaxf(fmaxf(a00.x, a01.x), fmaxf(a02.x, a03.x));
    float m0y = fmaxf(fmaxf(a00.y, a01.y), fmaxf(a02.y, a03.y));
    float m0z = fmaxf(fmaxf(a00.z, a01.z), fmaxf(a02.z, a03.z));
    float m0w = fmaxf(fmaxf(a00.w, a01.w), fmaxf(a02.w, a03.w));
    float m1x = fmaxf(fmaxf(a10.x, a11.x), fmaxf(a12.x, a13.x));
    float m1y = fmaxf(fmaxf(a10.y, a11.y), fmaxf(a12.y, a13.y));
    float m1z = fmaxf(fmaxf(a10.z, a11.z), fmaxf(a12.z, a13.z));
    float m1w = fmaxf(fmaxf(a10.w, a11.w), fmaxf(a12.w, a13.w));

    float acc = fmaxf(m0x, m0y) + fmaxf(m0z, m0w)
              + fmaxf(m1x, m1y) + fmaxf(m1z, m1w);

    // Block reduction: warp shuffle, then smem across 8 warps.
    #pragma unroll
    for (int off = 16; off > 0; off >>= 1)
        acc += __shfl_xor_sync(0xFFFFFFFFu, acc, off);

    __shared__ float warp_sums[8];
    const int warp = tid >> 5;
    const int lane = tid & 31;
    if (lane == 0) warp_sums[warp] = acc;
    __syncthreads();

    if (warp == 0) {
        float v = (lane < 8) ? warp_sums[lane] : 0.0f;
        #pragma unroll
        for (int off = 4; off > 0; off >>= 1)
            v += __shfl_xor_sync(0xFFFFFFFFu, v, off);

        if (lane == 0) {
            // Fire-and-forget: no fence, no return value -> block retires now.
            float contrib = v * SCALE_;
            asm volatile("red.relaxed.gpu.global.add.f32 [%0], %1;"
                         :: "l"(g_scratch + n), "f"(contrib) : "memory");
            // Release-ordered count: the scratch add above is visible to
            // whoever acquire-reads the counter at its final value.
            asm volatile("red.release.gpu.global.add.u32 [%0], %1;"
                         :: "l"(&g_done), "r"(1u) : "memory");

            // ---- finisher: block (0,0,0) only ----
            if ((blockIdx.x | blockIdx.y | blockIdx.z) == 0) {
                // Prefetch bias sum now; DRAM latency hides under the spin.
                float bsum = 0.0f;
                #pragma unroll
                for (int cc = 0; cc < C_; ++cc)
                    bsum += __ldg(&bias[cc]);

                unsigned int d;
                do {
                    asm volatile("ld.acquire.gpu.global.u32 %0, [%1];"
                                 : "=r"(d) : "l"(&g_done) : "memory");
                    if (d < TOTAL_BLOCKS) __nanosleep(128);
                } while (d < TOTAL_BLOCKS);

                // Acquire above + L1 bypass of REDs (+ per-launch L1 flush)
                // make plain loads of g_scratch coherent.
                float t[N_];
                #pragma unroll
                for (int nn = 0; nn < N_; ++nn) t[nn] = g_scratch[nn];
                #pragma unroll
                for (int nn = 0; nn < N_; ++nn) out[nn] = t[nn] + bsum;
                // Reset for next launch / graph replay.
                #pragma unroll
                for (int nn = 0; nn < N_; ++nn) g_scratch[nn] = 0.0f;
                asm volatile("st.relaxed.gpu.global.u32 [%0], %1;"
                             :: "l"(&g_done), "r"(0u) : "memory");
            }
        }
    }
}

extern "C" void kernel_launch(void* const* d_in, const int* in_sizes, int n_in,
                              void* d_out, int out_size) {
    const float* o    = (const float*)d_in[0];
    const float* bias = (const float*)d_in[1];
    float* out = (float*)d_out;

    dim3 grid(PD_, C_, N_);   // 16 x 32 x 16 = 8192 blocks, ~7 waves
    fused_pool_reduce_kernel<<<grid, 256>>>(o, bias, out);
}